// round 15
// baseline (speedup 1.0000x reference)
#include <cuda_runtime.h>
#include <cstdint>

// QuantizedEmbedding R15: TMA bulk reads + DIRECT STG.128 stores.
// Read frame from R14: one 8KB cp.async.bulk per token into 2 CTA-shared
// buffers (thread-0 issuer, prefetch 1 token ahead, one __syncthreads/token).
// Output goes registers -> STG.128 directly (no smem staging, no drain waits).
// smem = 16KB -> high occupancy for store issue bandwidth.

static constexpr int PACKED   = 2048;    // packed int32 per row (8KB)
static constexpr int NGROUPS  = 128;
static constexpr int DIM      = 4096;
static constexpr int THREADS  = 256;     // thread t: packed [t*8, t*8+8) -> group t>>1
static constexpr int TOKS     = 4;       // tokens per CTA (grid 4096)
static constexpr int ROW_B    = PACKED * 4;              // 8192 B
static constexpr int SMEM_IN    = 0;                     // 2 x 8KB
static constexpr int SMEM_MBAR  = 2 * ROW_B;             // 16384
static constexpr int SMEM_BYTES = SMEM_MBAR + 2 * 8 + 64;

__device__ __forceinline__ float4 dq2(int a, int b, float s) {
    float4 r;
    r.x = (float)(a / 16 - 8) * s;       // trunc-toward-zero high nibble
    r.y = (float)((a & 15) - 8) * s;     // nonneg mod-16 low nibble
    r.z = (float)(b / 16 - 8) * s;
    r.w = (float)((b & 15) - 8) * s;
    return r;
}

__device__ __forceinline__ void mbar_wait(uint32_t mbar, uint32_t parity) {
    asm volatile(
        "{\n\t"
        ".reg .pred P;\n\t"
        "WL_%=:\n\t"
        "mbarrier.try_wait.parity.acquire.cta.shared::cta.b64 P, [%0], %1, 0x989680;\n\t"
        "@P bra.uni WD_%=;\n\t"
        "bra.uni WL_%=;\n\t"
        "WD_%=:\n\t"
        "}"
        :: "r"(mbar), "r"(parity) : "memory");
}

__device__ __forceinline__ void issue_row_read(uint32_t dst, const int* src, uint32_t mbar) {
    asm volatile("fence.proxy.async.shared::cta;" ::: "memory");
    asm volatile("mbarrier.arrive.expect_tx.shared.b64 _, [%0], %1;"
                 :: "r"(mbar), "n"(ROW_B) : "memory");
    asm volatile("cp.async.bulk.shared::cta.global.mbarrier::complete_tx::bytes "
                 "[%0], [%1], %2, [%3];"
                 :: "r"(dst), "l"(src), "n"(ROW_B), "r"(mbar) : "memory");
}

__global__ void __launch_bounds__(THREADS)
qemb_kernel(const int* __restrict__ indices,
            const int* __restrict__ weight,
            const float* __restrict__ scales,
            float* __restrict__ out,
            int n_tokens)
{
    extern __shared__ __align__(128) unsigned char smem[];
    uint32_t sbase = (uint32_t)__cvta_generic_to_shared(smem);

    int t = threadIdx.x;
    long base = (long)blockIdx.x * TOKS;   // 16384 = 4096*4, exact

    uint32_t inb = sbase + SMEM_IN;        // 2 x 8KB
    uint32_t mbF = sbase + SMEM_MBAR;      // full[2]

    if (t == 0) {
        asm volatile("mbarrier.init.shared.b64 [%0], 1;" :: "r"(mbF)     : "memory");
        asm volatile("mbarrier.init.shared.b64 [%0], 1;" :: "r"(mbF + 8) : "memory");
        asm volatile("fence.proxy.async.shared::cta;" ::: "memory");
    }
    __syncthreads();

    int4 idx4 = __ldg(reinterpret_cast<const int4*>(indices + base));
    int idxs[TOKS] = { idx4.x, idx4.y, idx4.z, idx4.w };

    // prologue: issue token 0; prefetch all 4 scales (independent)
    if (t == 0)
        issue_row_read(inb, weight + (long)idxs[0] * PACKED, mbF);
    float sc[TOKS];
    #pragma unroll
    for (int j = 0; j < TOKS; j++)
        sc[j] = __ldg(scales + (long)idxs[j] * NGROUPS + (t >> 1));

    #pragma unroll
    for (int i = 0; i < TOKS; i++) {
        int bin = i & 1;

        // issue read for token i+1 into the other buffer.
        // Safe: that buffer was consumed at iter i-1, whose __syncthreads
        // (after all LDS) precedes this point.
        if (i + 1 < TOKS && t == 0)
            issue_row_read(inb + ((i + 1) & 1) * ROW_B,
                           weight + (long)idxs[i + 1] * PACKED,
                           mbF + ((i + 1) & 1) * 8);

        // wait for token i's row: buf bin fill #(i>>1) -> parity (i>>1)&1
        mbar_wait(mbF + bin * 8, (i >> 1) & 1);

        // thread t reads its 8 packed ints (32B) from the shared row
        uint32_t a0 = inb + bin * ROW_B + t * 32;
        int4 w0, w1;
        asm volatile("ld.shared.v4.u32 {%0,%1,%2,%3}, [%4];"
                     : "=r"(w0.x), "=r"(w0.y), "=r"(w0.z), "=r"(w0.w) : "r"(a0));
        asm volatile("ld.shared.v4.u32 {%0,%1,%2,%3}, [%4];"
                     : "=r"(w1.x), "=r"(w1.y), "=r"(w1.z), "=r"(w1.w) : "r"(a0 + 16));

        __syncthreads();   // all threads done with buf bin (enables next refill)

        // dequant -> direct STG.128 x4 (64B contiguous per thread, coalesced)
        float s = sc[i];
        float4* orow = reinterpret_cast<float4*>(out + (base + i) * DIM) + t * 4;
        orow[0] = dq2(w0.x, w0.y, s);
        orow[1] = dq2(w0.z, w0.w, s);
        orow[2] = dq2(w1.x, w1.y, s);
        orow[3] = dq2(w1.z, w1.w, s);
    }
}

extern "C" void kernel_launch(void* const* d_in, const int* in_sizes, int n_in,
                              void* d_out, int out_size)
{
    const int*   indices = (const int*)d_in[0];
    const int*   weight  = (const int*)d_in[1];
    const float* scales  = (const float*)d_in[2];
    float*       out     = (float*)d_out;

    int n_tokens = in_sizes[0];  // 16384

    cudaFuncSetAttribute(qemb_kernel,
                         cudaFuncAttributeMaxDynamicSharedMemorySize, SMEM_BYTES);
    cudaFuncSetAttribute(qemb_kernel,
                         cudaFuncAttributePreferredSharedMemoryCarveout, 100);

    int grid = n_tokens / TOKS;  // 4096
    qemb_kernel<<<grid, THREADS, SMEM_BYTES>>>(indices, weight, scales, out, n_tokens);
}